// round 15
// baseline (speedup 1.0000x reference)
#include <cuda_runtime.h>
#include <cuda_fp16.h>
#include <math.h>
#include <stdint.h>

// Problem dims: B=1, S=64, L=512, H=64, Dh=12, D=768, DFF=3072

// ---------------- scratch (static device globals; no allocation) ----------------
__device__ __half h_qkvT[(size_t)3 * 64 * 512 * 768];
__device__ float  g_logits[(size_t)64 * 512 * 512];    // f32 logits [h][i][j]
__device__ __half h_probs[(size_t)64 * 512 * 512];     // f16 softmax probs
__device__ float  g_tmp[(size_t)32768 * 768];          // rowout / colout / ffout (f32)
__device__ float  g_out1[(size_t)32768 * 768];
__device__ __half h_out1r[(size_t)32768 * 768];
__device__ float  g_y[(size_t)32768 * 768];
__device__ __half h_yr[(size_t)32768 * 768];
__device__ __half h_xr[(size_t)32768 * 768];
__device__ __half h_ffh[(size_t)32768 * 3072];
__device__ __half h_wr[(size_t)2304 * 768];            // weights transposed [N][K] f16
__device__ __half h_wc[(size_t)2304 * 768];
__device__ __half h_w1[(size_t)3072 * 768];
__device__ __half h_w2[(size_t)768 * 3072];

#define EPI_PLAIN_F32 0
#define EPI_RELU_H    1
#define EPI_QKV_ROW   2
#define EPI_QKV_COL   3
#define EPI_ROWOUT    4

__device__ __forceinline__ void cp16(void* s, const void* g) {
    unsigned sa = (unsigned)__cvta_generic_to_shared(s);
    asm volatile("cp.async.cg.shared.global [%0], [%1], 16;" :: "r"(sa), "l"(g));
}
__device__ __forceinline__ void cp_commit() {
    asm volatile("cp.async.commit_group;" ::: "memory");
}
__device__ __forceinline__ void ldm4(unsigned* r, unsigned addr) {
    asm volatile("ldmatrix.sync.aligned.m8n8.x4.shared.b16 {%0,%1,%2,%3}, [%4];"
                 : "=r"(r[0]), "=r"(r[1]), "=r"(r[2]), "=r"(r[3]) : "r"(addr));
}

template <int EPI>
__device__ __forceinline__ void epi_store(
    void* __restrict__ C, const float* __restrict__ bias,
    int N, size_t sC, int bz, int m, int n, float v)
{
    if (bias != nullptr) v += bias[n];
    if (EPI == EPI_PLAIN_F32) {
        ((float*)C)[sC * bz + (size_t)m * N + n] = v;
    } else if (EPI == EPI_RELU_H) {
        ((__half*)C)[(size_t)m * N + n] = __float2half(fmaxf(v, 0.f));
    } else if (EPI == EPI_QKV_ROW || EPI == EPI_QKV_COL) {
        const int s = m >> 9, ii = m & 511;
        const int part = n / 768, r = n - part * 768;
        const int h = r / 12, c = r - h * 12;
        const int sc = s * 12 + c;
        if (EPI == EPI_QKV_COL || part < 2)
            ((__half*)C)[(((size_t)part * 64 + h) * 512 + ii) * 768 + sc] = __float2half(v);
        else  // row-pass V: transposed [h][sc][i]
            ((__half*)C)[(size_t)2 * 64 * 512 * 768
                         + ((size_t)h * 768 + sc) * 512 + ii] = __float2half(v);
    } else { // EPI_ROWOUT
        const int s = n / 12, d = n - s * 12;
        ((float*)C)[((size_t)(s * 512 + m)) * 768 + (size_t)bz * 12 + d] = v;
    }
}

// ------------- f16 tensor-core GEMM (NT), cp.async 3-stage, k32 chunks ----------
// 128x128x32 block tile per stage, 4 warps (2x2), warp 64x64 via m16n8k16.
// Row stride 80B (64B data + 16 pad): rows' bank-quads {0,20,8,28,16,4,24,12}
// -> conflict-free ldmatrix. Syncs per 32 k (halved vs k16 stages).
#define HROW 80
#define HSTAGE (128 * HROW)            // 10240 B per operand per stage
#define HG_SMEM (6 * HSTAGE)           // 61440 B; 2 CTAs/SM
template <int EPI>
__global__ void __launch_bounds__(128, 2) hgemm(
    const __half* __restrict__ A, const __half* __restrict__ B,
    const float* __restrict__ bias, void* __restrict__ C,
    int M, int N, int K, size_t sA, size_t sB, size_t sC)
{
    extern __shared__ char smem[];
    const unsigned sbase = (unsigned)__cvta_generic_to_shared(smem);

    const int bz = blockIdx.z;
    const __half* Ab = A + sA * bz;
    const __half* Bb = B + sB * bz;
    const int m0 = blockIdx.y * 128, n0 = blockIdx.x * 128;
    const int t = threadIdx.x;
    const int lane = t & 31, warp = t >> 5;
    const int wm = (warp >> 1) * 64;
    const int wn = (warp & 1) * 64;
    const int lr = lane >> 2;
    const int lc = lane & 3;

    float acc[4][8][4];
#pragma unroll
    for (int i = 0; i < 4; i++)
#pragma unroll
        for (int j = 0; j < 8; j++)
#pragma unroll
            for (int e = 0; e < 4; e++) acc[i][j][e] = 0.f;

    auto issue = [&](int tile, int stage) {
        const int kt = tile * 32;
        char* as = smem + stage * HSTAGE;
        char* bs = smem + 3 * HSTAGE + stage * HSTAGE;
        const __half* ga = Ab + (size_t)(m0 + t) * K + kt;
        const __half* gb = Bb + (size_t)(n0 + t) * K + kt;
#pragma unroll
        for (int q = 0; q < 4; q++) {
            cp16(as + t * HROW + q * 16, ga + q * 8);
            cp16(bs + t * HROW + q * 16, gb + q * 8);
        }
    };

    // per-lane ldmatrix sub-offsets (within a k16 half)
    const unsigned aoff = (unsigned)((lane & 15) * HROW + ((lane >> 4) * 16));
    const unsigned boff = (unsigned)(((lane & 7) + ((lane >> 4) << 3)) * HROW
                                     + (((lane >> 3) & 1) * 16));

    auto compute = [&](int stage) {
        const unsigned asb = sbase + stage * HSTAGE;
        const unsigned bsb = sbase + 3 * HSTAGE + stage * HSTAGE;
#pragma unroll
        for (int h = 0; h < 2; h++) {           // two k16 halves of the k32 stage
            const unsigned hk = h * 32;         // byte offset of k-half
            unsigned af[4][4], bq[4][4];
#pragma unroll
            for (int mi = 0; mi < 4; mi++)
                ldm4(af[mi], asb + (wm + mi * 16) * HROW + aoff + hk);
#pragma unroll
            for (int q = 0; q < 4; q++)
                ldm4(bq[q], bsb + (wn + q * 16) * HROW + boff + hk);
#pragma unroll
            for (int mi = 0; mi < 4; mi++)
#pragma unroll
                for (int q = 0; q < 4; q++) {
                    asm volatile(
                        "mma.sync.aligned.m16n8k16.row.col.f32.f16.f16.f32 "
                        "{%0,%1,%2,%3},{%4,%5,%6,%7},{%8,%9},{%0,%1,%2,%3};"
                        : "+f"(acc[mi][2 * q][0]), "+f"(acc[mi][2 * q][1]),
                          "+f"(acc[mi][2 * q][2]), "+f"(acc[mi][2 * q][3])
                        : "r"(af[mi][0]), "r"(af[mi][1]), "r"(af[mi][2]), "r"(af[mi][3]),
                          "r"(bq[q][0]), "r"(bq[q][1]));
                    asm volatile(
                        "mma.sync.aligned.m16n8k16.row.col.f32.f16.f16.f32 "
                        "{%0,%1,%2,%3},{%4,%5,%6,%7},{%8,%9},{%0,%1,%2,%3};"
                        : "+f"(acc[mi][2 * q + 1][0]), "+f"(acc[mi][2 * q + 1][1]),
                          "+f"(acc[mi][2 * q + 1][2]), "+f"(acc[mi][2 * q + 1][3])
                        : "r"(af[mi][0]), "r"(af[mi][1]), "r"(af[mi][2]), "r"(af[mi][3]),
                          "r"(bq[q][2]), "r"(bq[q][3]));
                }
        }
    };

    const int nt = K >> 5;
    issue(0, 0); cp_commit();
    issue(1, 1); cp_commit();

    for (int i = 0; i < nt; i++) {
        asm volatile("cp.async.wait_group 1;" ::: "memory");
        __syncthreads();
        if (i + 2 < nt) issue(i + 2, (i + 2) % 3);
        cp_commit();
        compute(i % 3);
    }

    // epilogue
#pragma unroll
    for (int mi = 0; mi < 4; mi++) {
        const int mA = m0 + wm + mi * 16 + lr;
        const int mB = mA + 8;
#pragma unroll
        for (int ni = 0; ni < 8; ni++) {
            const int nA = n0 + wn + ni * 8 + 2 * lc;
            epi_store<EPI>(C, bias, N, sC, bz, mA, nA,     acc[mi][ni][0]);
            epi_store<EPI>(C, bias, N, sC, bz, mA, nA + 1, acc[mi][ni][1]);
            epi_store<EPI>(C, bias, N, sC, bz, mB, nA,     acc[mi][ni][2]);
            epi_store<EPI>(C, bias, N, sC, bz, mB, nA + 1, acc[mi][ni][3]);
        }
    }
}

// ---------------- prep: x f32 -> f16; ALL weights transposed in ONE launch -------
__global__ void __launch_bounds__(256) cvt_half(
    const float4* __restrict__ in, __half2* __restrict__ out, int n4)
{
    const int i = blockIdx.x * 256 + threadIdx.x;
    if (i < n4) {
        const float4 v = in[i];
        out[2 * i]     = __floats2half2_rn(v.x, v.y);
        out[2 * i + 1] = __floats2half2_rn(v.z, v.w);
    }
}

// z selects which weight; [K][N] f32 -> [N][K] f16. Out-of-range blocks exit.
__global__ void __launch_bounds__(256) tr_half_all(
    const float* __restrict__ w_row, const float* __restrict__ w_col,
    const float* __restrict__ w1, const float* __restrict__ w2,
    __half* __restrict__ wr, __half* __restrict__ wc,
    __half* __restrict__ w1t, __half* __restrict__ w2t)
{
    const int z = blockIdx.z;
    const float* w; __half* wt; int K, N;
    if (z == 0)      { w = w_row; wt = wr;  K = 768;  N = 2304; }
    else if (z == 1) { w = w_col; wt = wc;  K = 768;  N = 2304; }
    else if (z == 2) { w = w1;    wt = w1t; K = 768;  N = 3072; }
    else             { w = w2;    wt = w2t; K = 3072; N = 768;  }
    const int nb = blockIdx.x * 32, kb = blockIdx.y * 32;
    if (nb >= N || kb >= K) return;
    __shared__ float tile[32][33];
    const int tx = threadIdx.x & 31, ty0 = threadIdx.x >> 5;   // 32 x 8
#pragma unroll
    for (int i = 0; i < 4; i++) {
        const int ty = ty0 + i * 8;
        tile[ty][tx] = w[(size_t)(kb + ty) * N + nb + tx];
    }
    __syncthreads();
#pragma unroll
    for (int i = 0; i < 4; i++) {
        const int ty = ty0 + i * 8;
        wt[(size_t)(nb + ty) * K + kb + tx] = __float2half(tile[tx][ty]);
    }
}

// ---------------- softmax rows of 512: f32 logits -> f16 probs -------------------
__global__ void __launch_bounds__(256) softmax_rows(
    const float* __restrict__ logits, __half* __restrict__ probs)
{
    const int row = blockIdx.x * 8 + threadIdx.y;
    const float* p = logits + (size_t)row * 512;
    __half* po = probs + (size_t)row * 512;
    const int lane = threadIdx.x;
    float vals[16];
    float mx = -1e30f;
#pragma unroll
    for (int k = 0; k < 16; k++) {
        vals[k] = p[lane + k * 32];
        mx = fmaxf(mx, vals[k]);
    }
#pragma unroll
    for (int o = 16; o; o >>= 1) mx = fmaxf(mx, __shfl_xor_sync(0xffffffffu, mx, o));
    float sum = 0.f;
#pragma unroll
    for (int k = 0; k < 16; k++) {
        vals[k] = expf(vals[k] - mx);
        sum += vals[k];
    }
#pragma unroll
    for (int o = 16; o; o >>= 1) sum += __shfl_xor_sync(0xffffffffu, sum, o);
    const float inv = 1.f / sum;
#pragma unroll
    for (int k = 0; k < 16; k++) po[lane + k * 32] = __float2half(vals[k] * inv);
}

// ---------------- fused residual add + LayerNorm (rows of 768) -------------------
__device__ __forceinline__ void block_stats(float s1, float s2, int t,
                                            float& mean, float& inv)
{
#pragma unroll
    for (int o = 16; o; o >>= 1) {
        s1 += __shfl_xor_sync(0xffffffffu, s1, o);
        s2 += __shfl_xor_sync(0xffffffffu, s2, o);
    }
    __shared__ float sh1[8], sh2[8];
    const int w = t >> 5, ln = t & 31;
    if (ln == 0) { sh1[w] = s1; sh2[w] = s2; }
    __syncthreads();
    float S1 = 0.f, S2 = 0.f;
#pragma unroll
    for (int i = 0; i < 8; i++) { S1 += sh1[i]; S2 += sh2[i]; }
    mean = S1 * (1.f / 768.f);
    const float var = S2 * (1.f / 768.f) - mean * mean;
    inv = rsqrtf(var + 1e-5f);
    __syncthreads();
}

__global__ void __launch_bounds__(256) add_ln(
    const float* __restrict__ a, const float* __restrict__ b,
    const float* __restrict__ g, const float* __restrict__ be,
    float* __restrict__ out, __half* __restrict__ out_r)
{
    const int row = blockIdx.x;
    const int t = threadIdx.x;
    const size_t base = (size_t)row * 768;
    float v[3];
    float s1 = 0.f, s2 = 0.f;
#pragma unroll
    for (int j = 0; j < 3; j++) {
        const int idx = t + j * 256;
        const float x = a[base + idx] + b[base + idx];
        v[j] = x;
        s1 += x;
        s2 += x * x;
    }
    float mean, inv;
    block_stats(s1, s2, t, mean, inv);
#pragma unroll
    for (int j = 0; j < 3; j++) {
        const int idx = t + j * 256;
        const float o = (v[j] - mean) * inv * g[idx] + be[idx];
        out[base + idx] = o;
        if (out_r != nullptr) out_r[base + idx] = __float2half(o);
    }
}

__global__ void __launch_bounds__(256) add_ln2(
    const float* __restrict__ a, const float* __restrict__ b,
    const float* __restrict__ x,
    const float* __restrict__ g1, const float* __restrict__ be1,
    const float* __restrict__ g2, const float* __restrict__ be2,
    float* __restrict__ y, __half* __restrict__ y_r)
{
    const int row = blockIdx.x;
    const int t = threadIdx.x;
    const size_t base = (size_t)row * 768;
    float v[3];
    float s1 = 0.f, s2 = 0.f;
#pragma unroll
    for (int j = 0; j < 3; j++) {
        const int idx = t + j * 256;
        const float xv = a[base + idx] + b[base + idx];
        v[j] = xv;
        s1 += xv;
        s2 += xv * xv;
    }
    float mean, inv;
    block_stats(s1, s2, t, mean, inv);
    s1 = 0.f; s2 = 0.f;
#pragma unroll
    for (int j = 0; j < 3; j++) {
        const int idx = t + j * 256;
        const float u = (v[j] - mean) * inv * g1[idx] + be1[idx];
        const float w = x[base + idx] + u;
        v[j] = w;
        s1 += w;
        s2 += w * w;
    }
    block_stats(s1, s2, t, mean, inv);
#pragma unroll
    for (int j = 0; j < 3; j++) {
        const int idx = t + j * 256;
        const float o = (v[j] - mean) * inv * g2[idx] + be2[idx];
        y[base + idx] = o;
        y_r[base + idx] = __float2half(o);
    }
}

// ---------------- fused column attention: one block per (l, h) -------------------
__global__ void __launch_bounds__(64) col_attn(
    const __half* __restrict__ qkvc, float* __restrict__ out)
{
    const int l = blockIdx.x, h = blockIdx.y;
    __shared__ float sq[768], sk[768], sv[768];
    __shared__ float lg[64][65];
    const size_t PS = (size_t)64 * 512 * 768;
    const size_t base = ((size_t)h * 512 + l) * 768;
    const int t = threadIdx.x;
    for (int e = t; e < 768; e += 64) {
        sq[e] = __half2float(qkvc[base + e]);
        sk[e] = __half2float(qkvc[PS + base + e]);
        sv[e] = __half2float(qkvc[2 * PS + base + e]);
    }
    __syncthreads();

    float qi[12];
#pragma unroll
    for (int c = 0; c < 12; c++) qi[c] = sq[t * 12 + c];
    float mx = -1e30f;
    for (int j = 0; j < 64; j++) {
        float s = 0.f;
#pragma unroll
        for (int c = 0; c < 12; c++) s = fmaf(qi[c], sk[j * 12 + c], s);
        lg[t][j] = s;
        mx = fmaxf(mx, s);
    }
    float sum = 0.f;
    for (int j = 0; j < 64; j++) {
        const float e = expf(lg[t][j] - mx);
        lg[t][j] = e;
        sum += e;
    }
    const float inv = 1.f / sum;
    float o[12];
#pragma unroll
    for (int c = 0; c < 12; c++) o[c] = 0.f;
    for (int j = 0; j < 64; j++) {
        const float aw = lg[t][j] * inv;
#pragma unroll
        for (int c = 0; c < 12; c++) o[c] = fmaf(aw, sv[j * 12 + c], o[c]);
    }
    const size_t ob = ((size_t)t * 512 + l) * 768 + h * 12;
#pragma unroll
    for (int c = 0; c < 12; c++) out[ob + c] = o[c];
}

// ---------------- launch -----------------------------------------------------
extern "C" void kernel_launch(void* const* d_in, const int* in_sizes, int n_in,
                              void* d_out, int out_size)
{
    const float* x     = (const float*)d_in[0];
    const float* w_row = (const float*)d_in[1];
    const float* b_row = (const float*)d_in[2];
    const float* w_col = (const float*)d_in[3];
    const float* b_col = (const float*)d_in[4];
    const float* g_a1  = (const float*)d_in[5];
    const float* be_a1 = (const float*)d_in[6];
    const float* g_a2  = (const float*)d_in[7];
    const float* be_a2 = (const float*)d_in[8];
    const float* w1    = (const float*)d_in[9];
    const float* b1f   = (const float*)d_in[10];
    const float* w2    = (const float*)d_in[11];
    const float* b2f   = (const float*)d_in[12];
    const float* g_n1  = (const float*)d_in[13];
    const float* be_n1 = (const float*)d_in[14];
    const float* g_n2  = (const float*)d_in[15];
    const float* be_n2 = (const float*)d_in[16];
    float* out = (float*)d_out;

    __half *qkvT, *probs, *out1r, *yr, *xr, *ffh, *wr, *wc, *w1t, *w2t;
    float *logits, *tmp, *out1, *y;
    cudaGetSymbolAddress((void**)&qkvT, h_qkvT);
    cudaGetSymbolAddress((void**)&logits, g_logits);
    cudaGetSymbolAddress((void**)&probs, h_probs);
    cudaGetSymbolAddress((void**)&tmp, g_tmp);
    cudaGetSymbolAddress((void**)&out1, g_out1);
    cudaGetSymbolAddress((void**)&out1r, h_out1r);
    cudaGetSymbolAddress((void**)&y, g_y);
    cudaGetSymbolAddress((void**)&yr, h_yr);
    cudaGetSymbolAddress((void**)&xr, h_xr);
    cudaGetSymbolAddress((void**)&ffh, h_ffh);
    cudaGetSymbolAddress((void**)&wr, h_wr);
    cudaGetSymbolAddress((void**)&wc, h_wc);
    cudaGetSymbolAddress((void**)&w1t, h_w1);
    cudaGetSymbolAddress((void**)&w2t, h_w2);

    cudaFuncSetAttribute(hgemm<EPI_PLAIN_F32>,
                         cudaFuncAttributeMaxDynamicSharedMemorySize, HG_SMEM);
    cudaFuncSetAttribute(hgemm<EPI_PLAIN_F32>,
                         cudaFuncAttributePreferredSharedMemoryCarveout, 100);
    cudaFuncSetAttribute(hgemm<EPI_RELU_H>,
                         cudaFuncAttributeMaxDynamicSharedMemorySize, HG_SMEM);
    cudaFuncSetAttribute(hgemm<EPI_RELU_H>,
                         cudaFuncAttributePreferredSharedMemoryCarveout, 100);
    cudaFuncSetAttribute(hgemm<EPI_QKV_ROW>,
                         cudaFuncAttributeMaxDynamicSharedMemorySize, HG_SMEM);
    cudaFuncSetAttribute(hgemm<EPI_QKV_ROW>,
                         cudaFuncAttributePreferredSharedMemoryCarveout, 100);
    cudaFuncSetAttribute(hgemm<EPI_QKV_COL>,
                         cudaFuncAttributeMaxDynamicSharedMemorySize, HG_SMEM);
    cudaFuncSetAttribute(hgemm<EPI_QKV_COL>,
                         cudaFuncAttributePreferredSharedMemoryCarveout, 100);
    cudaFuncSetAttribute(hgemm<EPI_ROWOUT>,
                         cudaFuncAttributeMaxDynamicSharedMemorySize, HG_SMEM);
    cudaFuncSetAttribute(hgemm<EPI_ROWOUT>,
                         cudaFuncAttributePreferredSharedMemoryCarveout, 100);

    const size_t PS = (size_t)64 * 512 * 768;   // per-part stride in qkvT (elements)

    // prep (2 launches so ncu -s 5 lands on the AV hgemm below)
    cvt_half<<<(32768 * 768 / 4 + 255) / 256, 256>>>(
        (const float4*)x, (__half2*)xr, 32768 * 768 / 4);
    tr_half_all<<<dim3(96, 96, 4), 256>>>(w_row, w_col, w1, w2, wr, wc, w1t, w2t);

    // 1) row QKV: [32768,768] @ wr^T -> qkvT (q,k normal; v transposed per head)
    hgemm<EPI_QKV_ROW><<<dim3(18, 256), 128, HG_SMEM>>>(
        xr, wr, b_row, qkvT, 32768, 2304, 768, 0, 0, 0);

    // 2) row-attn logits per head: q[512,768] @ k[512,768]^T -> f32, batch 64
    hgemm<EPI_PLAIN_F32><<<dim3(4, 4, 64), 128, HG_SMEM>>>(
        qkvT, qkvT + PS, nullptr, logits, 512, 512, 768,
        (size_t)512 * 768, (size_t)512 * 768, (size_t)512 * 512);

    // 3) softmax -> f16 probs
    softmax_rows<<<4096, dim3(32, 8)>>>(logits, probs);

    // 4) row-attn AV: probs[512,512] @ vT[768,512]^T -> scatter [s,i,h,d] f32
    hgemm<EPI_ROWOUT><<<dim3(6, 4, 64), 128, HG_SMEM>>>(
        probs, qkvT + 2 * PS, nullptr, tmp, 512, 768, 512,
        (size_t)512 * 512, (size_t)768 * 512, 0);

    // 5) out1 = LN(x + rowout), plus f16 copy
    add_ln<<<32768, 256>>>(x, tmp, g_a1, be_a1, out1, out1r);

    // 6) col QKV (all parts normal layout)
    hgemm<EPI_QKV_COL><<<dim3(18, 256), 128, HG_SMEM>>>(
        out1r, wc, b_col, qkvT, 32768, 2304, 768, 0, 0, 0);

    // 7) fused col attention per (l, h)
    col_attn<<<dim3(512, 64), 64>>>(qkvT, tmp);

    // 8+9) y = LN(x + LN(out1 + colout)), plus f16 copy
    add_ln2<<<32768, 256>>>(out1, tmp, x, g_a2, be_a2, g_n1, be_n1, y, yr);

    // 10) FFN up + ReLU -> f16 hidden
    hgemm<EPI_RELU_H><<<dim3(24, 256), 128, HG_SMEM>>>(
        yr, w1t, b1f, ffh, 32768, 3072, 768, 0, 0, 0);

    // 11) FFN down -> f32
    hgemm<EPI_PLAIN_F32><<<dim3(6, 256), 128, HG_SMEM>>>(
        ffh, w2t, b2f, tmp, 32768, 768, 3072, 0, 0, 0);

    // 12) out = LN(y + ff)
    add_ln<<<32768, 256>>>(y, tmp, g_n2, be_n2, out, nullptr);
}

// round 16
// speedup vs baseline: 1.1472x; 1.1472x over previous
#include <cuda_runtime.h>
#include <cuda_fp16.h>
#include <math.h>
#include <stdint.h>

// Problem dims: B=1, S=64, L=512, H=64, Dh=12, D=768, DFF=3072

// ---------------- scratch (static device globals; no allocation) ----------------
__device__ __half h_qkvT[(size_t)3 * 64 * 512 * 768];
__device__ float  g_logits[(size_t)64 * 512 * 512];    // f32 logits [h][i][j]
__device__ __half h_probs[(size_t)64 * 512 * 512];     // f16 softmax probs
__device__ float  g_tmp[(size_t)32768 * 768];          // rowout / colout / ffout (f32)
__device__ float  g_out1[(size_t)32768 * 768];
__device__ __half h_out1r[(size_t)32768 * 768];
__device__ float  g_y[(size_t)32768 * 768];
__device__ __half h_yr[(size_t)32768 * 768];
__device__ __half h_xr[(size_t)32768 * 768];
__device__ __half h_ffh[(size_t)32768 * 3072];
__device__ __half h_wr[(size_t)2304 * 768];            // weights transposed [N][K] f16
__device__ __half h_wc[(size_t)2304 * 768];
__device__ __half h_w1[(size_t)3072 * 768];
__device__ __half h_w2[(size_t)768 * 3072];

#define EPI_PLAIN_F32 0
#define EPI_RELU_H    1
#define EPI_QKV_ROW   2
#define EPI_QKV_COL   3
#define EPI_ROWOUT    4

__device__ __forceinline__ void cp16(void* s, const void* g) {
    unsigned sa = (unsigned)__cvta_generic_to_shared(s);
    asm volatile("cp.async.cg.shared.global [%0], [%1], 16;" :: "r"(sa), "l"(g));
}
__device__ __forceinline__ void cp_commit() {
    asm volatile("cp.async.commit_group;" ::: "memory");
}
__device__ __forceinline__ void ldm4(unsigned* r, unsigned addr) {
    asm volatile("ldmatrix.sync.aligned.m8n8.x4.shared.b16 {%0,%1,%2,%3}, [%4];"
                 : "=r"(r[0]), "=r"(r[1]), "=r"(r[2]), "=r"(r[3]) : "r"(addr));
}

template <int EPI>
__device__ __forceinline__ void epi_store(
    void* __restrict__ C, const float* __restrict__ bias,
    int N, size_t sC, int bz, int m, int n, float v)
{
    if (bias != nullptr) v += bias[n];
    if (EPI == EPI_PLAIN_F32) {
        ((float*)C)[sC * bz + (size_t)m * N + n] = v;
    } else if (EPI == EPI_RELU_H) {
        ((__half*)C)[(size_t)m * N + n] = __float2half(fmaxf(v, 0.f));
    } else if (EPI == EPI_QKV_ROW || EPI == EPI_QKV_COL) {
        const int s = m >> 9, ii = m & 511;
        const int part = n / 768, r = n - part * 768;
        const int h = r / 12, c = r - h * 12;
        const int sc = s * 12 + c;
        if (EPI == EPI_QKV_COL || part < 2)
            ((__half*)C)[(((size_t)part * 64 + h) * 512 + ii) * 768 + sc] = __float2half(v);
        else  // row-pass V: transposed [h][sc][i]
            ((__half*)C)[(size_t)2 * 64 * 512 * 768
                         + ((size_t)h * 768 + sc) * 512 + ii] = __float2half(v);
    } else { // EPI_ROWOUT
        const int s = n / 12, d = n - s * 12;
        ((float*)C)[((size_t)(s * 512 + m)) * 768 + (size_t)bz * 12 + d] = v;
    }
}

// ------------- f16 tensor-core GEMM (NT), cp.async 3-stage, k16 stages ----------
// 128x128x16 block tile, 8 warps (2x4), each warp 64x32 via 4x4 m16n8k16.
// 256 threads/CTA, 2 CTAs/SM -> 16 warps/SM for latency hiding (R14 fix).
// A [M][K] f16 k-contig, B [N][K] f16 k-contig.
// smem rows 32B data padded to 48B stride -> conflict-free ldmatrix.
#define HROW 48
#define HSTAGE (128 * HROW)            // 6144 B per operand per stage
#define HG_SMEM (6 * HSTAGE)           // 36864 B; 2 CTAs/SM trivially
template <int EPI>
__global__ void __launch_bounds__(256, 2) hgemm(
    const __half* __restrict__ A, const __half* __restrict__ B,
    const float* __restrict__ bias, void* __restrict__ C,
    int M, int N, int K, size_t sA, size_t sB, size_t sC)
{
    extern __shared__ char smem[];
    const unsigned sbase = (unsigned)__cvta_generic_to_shared(smem);

    const int bz = blockIdx.z;
    const __half* Ab = A + sA * bz;
    const __half* Bb = B + sB * bz;
    const int m0 = blockIdx.y * 128, n0 = blockIdx.x * 128;
    const int t = threadIdx.x;
    const int lane = t & 31, warp = t >> 5;
    const int wm = (warp >> 2) * 64;   // 2 warps in m
    const int wn = (warp & 3) * 32;    // 4 warps in n
    const int lr = lane >> 2;
    const int lc = lane & 3;

    float acc[4][4][4];
#pragma unroll
    for (int i = 0; i < 4; i++)
#pragma unroll
        for (int j = 0; j < 4; j++)
#pragma unroll
            for (int e = 0; e < 4; e++) acc[i][j][e] = 0.f;

    // loader: 256 threads, 1 cp16 per operand each (128 rows x 2 halves)
    const int l_row = t >> 1, l_off = (t & 1) * 16;
    auto issue = [&](int tile, int stage) {
        const int kt = tile * 16 + (t & 1) * 8;
        char* as = smem + stage * HSTAGE;
        char* bs = smem + 3 * HSTAGE + stage * HSTAGE;
        cp16(as + l_row * HROW + l_off, Ab + (size_t)(m0 + l_row) * K + kt);
        cp16(bs + l_row * HROW + l_off, Bb + (size_t)(n0 + l_row) * K + kt);
    };

    // per-lane ldmatrix sub-offsets
    const unsigned aoff = (unsigned)((lane & 15) * HROW + ((lane >> 4) * 16));
    const unsigned boff = (unsigned)(((lane & 7) + ((lane >> 4) << 3)) * HROW
                                     + (((lane >> 3) & 1) * 16));

    auto compute = [&](int stage) {
        const unsigned asb = sbase + stage * HSTAGE;
        const unsigned bsb = sbase + 3 * HSTAGE + stage * HSTAGE;
        unsigned af[4][4], bq[2][4];
#pragma unroll
        for (int mi = 0; mi < 4; mi++)
            ldm4(af[mi], asb + (wm + mi * 16) * HROW + aoff);
#pragma unroll
        for (int q = 0; q < 2; q++)
            ldm4(bq[q], bsb + (wn + q * 16) * HROW + boff);
#pragma unroll
        for (int mi = 0; mi < 4; mi++)
#pragma unroll
            for (int q = 0; q < 2; q++) {
                asm volatile(
                    "mma.sync.aligned.m16n8k16.row.col.f32.f16.f16.f32 "
                    "{%0,%1,%2,%3},{%4,%5,%6,%7},{%8,%9},{%0,%1,%2,%3};"
                    : "+f"(acc[mi][2 * q][0]), "+f"(acc[mi][2 * q][1]),
                      "+f"(acc[mi][2 * q][2]), "+f"(acc[mi][2 * q][3])
                    : "r"(af[mi][0]), "r"(af[mi][1]), "r"(af[mi][2]), "r"(af[mi][3]),
                      "r"(bq[q][0]), "r"(bq[q][1]));
                asm volatile(
                    "mma.sync.aligned.m16n8k16.row.col.f32.f16.f16.f32 "
                    "{%0,%1,%2,%3},{%4,%5,%6,%7},{%8,%9},{%0,%1,%2,%3};"
                    : "+f"(acc[mi][2 * q + 1][0]), "+f"(acc[mi][2 * q + 1][1]),
                      "+f"(acc[mi][2 * q + 1][2]), "+f"(acc[mi][2 * q + 1][3])
                    : "r"(af[mi][0]), "r"(af[mi][1]), "r"(af[mi][2]), "r"(af[mi][3]),
                      "r"(bq[q][2]), "r"(bq[q][3]));
            }
    };

    const int nt = K >> 4;
    issue(0, 0); cp_commit();
    issue(1, 1); cp_commit();

    for (int i = 0; i < nt; i++) {
        asm volatile("cp.async.wait_group 1;" ::: "memory");
        __syncthreads();
        if (i + 2 < nt) issue(i + 2, (i + 2) % 3);
        cp_commit();
        compute(i % 3);
    }

    // epilogue
#pragma unroll
    for (int mi = 0; mi < 4; mi++) {
        const int mA = m0 + wm + mi * 16 + lr;
        const int mB = mA + 8;
#pragma unroll
        for (int ni = 0; ni < 4; ni++) {
            const int nA = n0 + wn + ni * 8 + 2 * lc;
            epi_store<EPI>(C, bias, N, sC, bz, mA, nA,     acc[mi][ni][0]);
            epi_store<EPI>(C, bias, N, sC, bz, mA, nA + 1, acc[mi][ni][1]);
            epi_store<EPI>(C, bias, N, sC, bz, mB, nA,     acc[mi][ni][2]);
            epi_store<EPI>(C, bias, N, sC, bz, mB, nA + 1, acc[mi][ni][3]);
        }
    }
}

// ---------------- prep: x f32 -> f16; ALL weights transposed in ONE launch -------
__global__ void __launch_bounds__(256) cvt_half(
    const float4* __restrict__ in, __half2* __restrict__ out, int n4)
{
    const int i = blockIdx.x * 256 + threadIdx.x;
    if (i < n4) {
        const float4 v = in[i];
        out[2 * i]     = __floats2half2_rn(v.x, v.y);
        out[2 * i + 1] = __floats2half2_rn(v.z, v.w);
    }
}

__global__ void __launch_bounds__(256) tr_half_all(
    const float* __restrict__ w_row, const float* __restrict__ w_col,
    const float* __restrict__ w1, const float* __restrict__ w2,
    __half* __restrict__ wr, __half* __restrict__ wc,
    __half* __restrict__ w1t, __half* __restrict__ w2t)
{
    const int z = blockIdx.z;
    const float* w; __half* wt; int K, N;
    if (z == 0)      { w = w_row; wt = wr;  K = 768;  N = 2304; }
    else if (z == 1) { w = w_col; wt = wc;  K = 768;  N = 2304; }
    else if (z == 2) { w = w1;    wt = w1t; K = 768;  N = 3072; }
    else             { w = w2;    wt = w2t; K = 3072; N = 768;  }
    const int nb = blockIdx.x * 32, kb = blockIdx.y * 32;
    if (nb >= N || kb >= K) return;
    __shared__ float tile[32][33];
    const int tx = threadIdx.x & 31, ty0 = threadIdx.x >> 5;   // 32 x 8
#pragma unroll
    for (int i = 0; i < 4; i++) {
        const int ty = ty0 + i * 8;
        tile[ty][tx] = w[(size_t)(kb + ty) * N + nb + tx];
    }
    __syncthreads();
#pragma unroll
    for (int i = 0; i < 4; i++) {
        const int ty = ty0 + i * 8;
        wt[(size_t)(nb + ty) * K + kb + tx] = __float2half(tile[tx][ty]);
    }
}

// ---------------- softmax rows of 512: f32 logits -> f16 probs -------------------
__global__ void __launch_bounds__(256) softmax_rows(
    const float* __restrict__ logits, __half* __restrict__ probs)
{
    const int row = blockIdx.x * 8 + threadIdx.y;
    const float* p = logits + (size_t)row * 512;
    __half* po = probs + (size_t)row * 512;
    const int lane = threadIdx.x;
    float vals[16];
    float mx = -1e30f;
#pragma unroll
    for (int k = 0; k < 16; k++) {
        vals[k] = p[lane + k * 32];
        mx = fmaxf(mx, vals[k]);
    }
#pragma unroll
    for (int o = 16; o; o >>= 1) mx = fmaxf(mx, __shfl_xor_sync(0xffffffffu, mx, o));
    float sum = 0.f;
#pragma unroll
    for (int k = 0; k < 16; k++) {
        vals[k] = expf(vals[k] - mx);
        sum += vals[k];
    }
#pragma unroll
    for (int o = 16; o; o >>= 1) sum += __shfl_xor_sync(0xffffffffu, sum, o);
    const float inv = 1.f / sum;
#pragma unroll
    for (int k = 0; k < 16; k++) po[lane + k * 32] = __float2half(vals[k] * inv);
}

// ---------------- fused residual add + LayerNorm (rows of 768) -------------------
__device__ __forceinline__ void block_stats(float s1, float s2, int t,
                                            float& mean, float& inv)
{
#pragma unroll
    for (int o = 16; o; o >>= 1) {
        s1 += __shfl_xor_sync(0xffffffffu, s1, o);
        s2 += __shfl_xor_sync(0xffffffffu, s2, o);
    }
    __shared__ float sh1[8], sh2[8];
    const int w = t >> 5, ln = t & 31;
    if (ln == 0) { sh1[w] = s1; sh2[w] = s2; }
    __syncthreads();
    float S1 = 0.f, S2 = 0.f;
#pragma unroll
    for (int i = 0; i < 8; i++) { S1 += sh1[i]; S2 += sh2[i]; }
    mean = S1 * (1.f / 768.f);
    const float var = S2 * (1.f / 768.f) - mean * mean;
    inv = rsqrtf(var + 1e-5f);
    __syncthreads();
}

__global__ void __launch_bounds__(256) add_ln(
    const float* __restrict__ a, const float* __restrict__ b,
    const float* __restrict__ g, const float* __restrict__ be,
    float* __restrict__ out, __half* __restrict__ out_r)
{
    const int row = blockIdx.x;
    const int t = threadIdx.x;
    const size_t base = (size_t)row * 768;
    float v[3];
    float s1 = 0.f, s2 = 0.f;
#pragma unroll
    for (int j = 0; j < 3; j++) {
        const int idx = t + j * 256;
        const float x = a[base + idx] + b[base + idx];
        v[j] = x;
        s1 += x;
        s2 += x * x;
    }
    float mean, inv;
    block_stats(s1, s2, t, mean, inv);
#pragma unroll
    for (int j = 0; j < 3; j++) {
        const int idx = t + j * 256;
        const float o = (v[j] - mean) * inv * g[idx] + be[idx];
        out[base + idx] = o;
        if (out_r != nullptr) out_r[base + idx] = __float2half(o);
    }
}

__global__ void __launch_bounds__(256) add_ln2(
    const float* __restrict__ a, const float* __restrict__ b,
    const float* __restrict__ x,
    const float* __restrict__ g1, const float* __restrict__ be1,
    const float* __restrict__ g2, const float* __restrict__ be2,
    float* __restrict__ y, __half* __restrict__ y_r)
{
    const int row = blockIdx.x;
    const int t = threadIdx.x;
    const size_t base = (size_t)row * 768;
    float v[3];
    float s1 = 0.f, s2 = 0.f;
#pragma unroll
    for (int j = 0; j < 3; j++) {
        const int idx = t + j * 256;
        const float xv = a[base + idx] + b[base + idx];
        v[j] = xv;
        s1 += xv;
        s2 += xv * xv;
    }
    float mean, inv;
    block_stats(s1, s2, t, mean, inv);
    s1 = 0.f; s2 = 0.f;
#pragma unroll
    for (int j = 0; j < 3; j++) {
        const int idx = t + j * 256;
        const float u = (v[j] - mean) * inv * g1[idx] + be1[idx];
        const float w = x[base + idx] + u;
        v[j] = w;
        s1 += w;
        s2 += w * w;
    }
    block_stats(s1, s2, t, mean, inv);
#pragma unroll
    for (int j = 0; j < 3; j++) {
        const int idx = t + j * 256;
        const float o = (v[j] - mean) * inv * g2[idx] + be2[idx];
        y[base + idx] = o;
        y_r[base + idx] = __float2half(o);
    }
}

// ---------------- fused column attention: one block per (l, h) -------------------
__global__ void __launch_bounds__(64) col_attn(
    const __half* __restrict__ qkvc, float* __restrict__ out)
{
    const int l = blockIdx.x, h = blockIdx.y;
    __shared__ float sq[768], sk[768], sv[768];
    __shared__ float lg[64][65];
    const size_t PS = (size_t)64 * 512 * 768;
    const size_t base = ((size_t)h * 512 + l) * 768;
    const int t = threadIdx.x;
    for (int e = t; e < 768; e += 64) {
        sq[e] = __half2float(qkvc[base + e]);
        sk[e] = __half2float(qkvc[PS + base + e]);
        sv[e] = __half2float(qkvc[2 * PS + base + e]);
    }
    __syncthreads();

    float qi[12];
#pragma unroll
    for (int c = 0; c < 12; c++) qi[c] = sq[t * 12 + c];
    float mx = -1e30f;
    for (int j = 0; j < 64; j++) {
        float s = 0.f;
#pragma unroll
        for (int c = 0; c < 12; c++) s = fmaf(qi[c], sk[j * 12 + c], s);
        lg[t][j] = s;
        mx = fmaxf(mx, s);
    }
    float sum = 0.f;
    for (int j = 0; j < 64; j++) {
        const float e = expf(lg[t][j] - mx);
        lg[t][j] = e;
        sum += e;
    }
    const float inv = 1.f / sum;
    float o[12];
#pragma unroll
    for (int c = 0; c < 12; c++) o[c] = 0.f;
    for (int j = 0; j < 64; j++) {
        const float aw = lg[t][j] * inv;
#pragma unroll
        for (int c = 0; c < 12; c++) o[c] = fmaf(aw, sv[j * 12 + c], o[c]);
    }
    const size_t ob = ((size_t)t * 512 + l) * 768 + h * 12;
#pragma unroll
    for (int c = 0; c < 12; c++) out[ob + c] = o[c];
}

// ---------------- launch -----------------------------------------------------
extern "C" void kernel_launch(void* const* d_in, const int* in_sizes, int n_in,
                              void* d_out, int out_size)
{
    const float* x     = (const float*)d_in[0];
    const float* w_row = (const float*)d_in[1];
    const float* b_row = (const float*)d_in[2];
    const float* w_col = (const float*)d_in[3];
    const float* b_col = (const float*)d_in[4];
    const float* g_a1  = (const float*)d_in[5];
    const float* be_a1 = (const float*)d_in[6];
    const float* g_a2  = (const float*)d_in[7];
    const float* be_a2 = (const float*)d_in[8];
    const float* w1    = (const float*)d_in[9];
    const float* b1f   = (const float*)d_in[10];
    const float* w2    = (const float*)d_in[11];
    const float* b2f   = (const float*)d_in[12];
    const float* g_n1  = (const float*)d_in[13];
    const float* be_n1 = (const float*)d_in[14];
    const float* g_n2  = (const float*)d_in[15];
    const float* be_n2 = (const float*)d_in[16];
    float* out = (float*)d_out;

    __half *qkvT, *probs, *out1r, *yr, *xr, *ffh, *wr, *wc, *w1t, *w2t;
    float *logits, *tmp, *out1, *y;
    cudaGetSymbolAddress((void**)&qkvT, h_qkvT);
    cudaGetSymbolAddress((void**)&logits, g_logits);
    cudaGetSymbolAddress((void**)&probs, h_probs);
    cudaGetSymbolAddress((void**)&tmp, g_tmp);
    cudaGetSymbolAddress((void**)&out1, g_out1);
    cudaGetSymbolAddress((void**)&out1r, h_out1r);
    cudaGetSymbolAddress((void**)&y, g_y);
    cudaGetSymbolAddress((void**)&yr, h_yr);
    cudaGetSymbolAddress((void**)&xr, h_xr);
    cudaGetSymbolAddress((void**)&ffh, h_ffh);
    cudaGetSymbolAddress((void**)&wr, h_wr);
    cudaGetSymbolAddress((void**)&wc, h_wc);
    cudaGetSymbolAddress((void**)&w1t, h_w1);
    cudaGetSymbolAddress((void**)&w2t, h_w2);

    cudaFuncSetAttribute(hgemm<EPI_PLAIN_F32>,
                         cudaFuncAttributeMaxDynamicSharedMemorySize, HG_SMEM);
    cudaFuncSetAttribute(hgemm<EPI_PLAIN_F32>,
                         cudaFuncAttributePreferredSharedMemoryCarveout, 100);
    cudaFuncSetAttribute(hgemm<EPI_RELU_H>,
                         cudaFuncAttributeMaxDynamicSharedMemorySize, HG_SMEM);
    cudaFuncSetAttribute(hgemm<EPI_RELU_H>,
                         cudaFuncAttributePreferredSharedMemoryCarveout, 100);
    cudaFuncSetAttribute(hgemm<EPI_QKV_ROW>,
                         cudaFuncAttributeMaxDynamicSharedMemorySize, HG_SMEM);
    cudaFuncSetAttribute(hgemm<EPI_QKV_ROW>,
                         cudaFuncAttributePreferredSharedMemoryCarveout, 100);
    cudaFuncSetAttribute(hgemm<EPI_QKV_COL>,
                         cudaFuncAttributeMaxDynamicSharedMemorySize, HG_SMEM);
    cudaFuncSetAttribute(hgemm<EPI_QKV_COL>,
                         cudaFuncAttributePreferredSharedMemoryCarveout, 100);
    cudaFuncSetAttribute(hgemm<EPI_ROWOUT>,
                         cudaFuncAttributeMaxDynamicSharedMemorySize, HG_SMEM);
    cudaFuncSetAttribute(hgemm<EPI_ROWOUT>,
                         cudaFuncAttributePreferredSharedMemoryCarveout, 100);

    const size_t PS = (size_t)64 * 512 * 768;   // per-part stride in qkvT (elements)

    // prep
    cvt_half<<<(32768 * 768 / 4 + 255) / 256, 256>>>(
        (const float4*)x, (__half2*)xr, 32768 * 768 / 4);
    tr_half_all<<<dim3(96, 96, 4), 256>>>(w_row, w_col, w1, w2, wr, wc, w1t, w2t);

    // 1) row QKV: [32768,768] @ wr^T -> qkvT (q,k normal; v transposed per head)
    hgemm<EPI_QKV_ROW><<<dim3(18, 256), 256, HG_SMEM>>>(
        xr, wr, b_row, qkvT, 32768, 2304, 768, 0, 0, 0);

    // 2) row-attn logits per head: q[512,768] @ k[512,768]^T -> f32, batch 64
    hgemm<EPI_PLAIN_F32><<<dim3(4, 4, 64), 256, HG_SMEM>>>(
        qkvT, qkvT + PS, nullptr, logits, 512, 512, 768,
        (size_t)512 * 768, (size_t)512 * 768, (size_t)512 * 512);

    // 3) softmax -> f16 probs
    softmax_rows<<<4096, dim3(32, 8)>>>(logits, probs);

    // 4) row-attn AV: probs[512,512] @ vT[768,512]^T -> scatter [s,i,h,d] f32
    hgemm<EPI_ROWOUT><<<dim3(6, 4, 64), 256, HG_SMEM>>>(
        probs, qkvT + 2 * PS, nullptr, tmp, 512, 768, 512,
        (size_t)512 * 512, (size_t)768 * 512, 0);

    // 5) out1 = LN(x + rowout), plus f16 copy
    add_ln<<<32768, 256>>>(x, tmp, g_a1, be_a1, out1, out1r);

    // 6) col QKV (all parts normal layout)
    hgemm<EPI_QKV_COL><<<dim3(18, 256), 256, HG_SMEM>>>(
        out1r, wc, b_col, qkvT, 32768, 2304, 768, 0, 0, 0);

    // 7) fused col attention per (l, h)
    col_attn<<<dim3(512, 64), 64>>>(qkvT, tmp);

    // 8+9) y = LN(x + LN(out1 + colout)), plus f16 copy
    add_ln2<<<32768, 256>>>(out1, tmp, x, g_a2, be_a2, g_n1, be_n1, y, yr);

    // 10) FFN up + ReLU -> f16 hidden
    hgemm<EPI_RELU_H><<<dim3(24, 256), 256, HG_SMEM>>>(
        yr, w1t, b1f, ffh, 32768, 3072, 768, 0, 0, 0);

    // 11) FFN down -> f32
    hgemm<EPI_PLAIN_F32><<<dim3(6, 256), 256, HG_SMEM>>>(
        ffh, w2t, b2f, tmp, 32768, 768, 3072, 0, 0, 0);

    // 12) out = LN(y + ff)
    add_ln<<<32768, 256>>>(y, tmp, g_n2, be_n2, out, nullptr);
}